// round 11
// baseline (speedup 1.0000x reference)
#include <cuda_runtime.h>
#include <cuda_bf16.h>

#define NN 50000
#define NE 800000
#define SCAN_BLOCKS 49   // ceil(50000/1024)

// ---- scratch (__device__ globals; no allocation allowed) -------------------
__device__ float4 g_y[NN * 32];     // {ys, yv0..2} post-lin1
__device__ float4 g_midA[NN * 32];  // segment sums {o_s_a, o_v_a}
__device__ float4 g_midB[NN * 32];  // segment sums {o_s_b, o_v_b}
__device__ int    g_count[NN];      // dst degree histogram
__device__ int    g_start[NN];      // CSR offsets
__device__ int    g_cursor[NN];     // scatter cursors
__device__ int    g_bsum[SCAN_BLOCKS];
__device__ int2   g_sd[NE];         // sorted {src, dst}
__device__ float4 g_avs[NE];        // sorted edge_attr
__device__ int    g_eid[NE];        // sorted original edge id
__device__ float  g_hs[NE * 8];     // h in SORTED order

__device__ __forceinline__ void red_add_f4(float4* p, float4 v) {
    asm volatile("red.global.add.v4.f32 [%0], {%1, %2, %3, %4};"
                 :: "l"(p), "f"(v.x), "f"(v.y), "f"(v.z), "f"(v.w)
                 : "memory");
}

// ---------------------------------------------------------------------------
// Kernel 1: per-node prep. ys/yv = lin1(x); self-connection -> out.
// Coalesced row load (1 LDG.128/lane). Zeroes g_count and mid accumulators.
// ---------------------------------------------------------------------------
__global__ void node_prep_kernel(const float* __restrict__ nf,
                                 const float* __restrict__ nattr,
                                 const float* __restrict__ W1s,
                                 const float* __restrict__ W1v,
                                 const float* __restrict__ Wscs,
                                 const float* __restrict__ Wscv,
                                 float* __restrict__ out) {
    __shared__ float2 sW1[1024];    // [u][w] -> {W1s, W1v}
    __shared__ float2 sWsc[4096];   // [u][sp][w] -> {Wscs, Wscv}
    __shared__ float4 sRaw4[8][32];
    __shared__ float4 sRow[8][32];  // packed {xs, xv0, xv1, xv2} per u

    const int tid = threadIdx.x;
    for (int i = tid; i < 1024; i += 256) sW1[i] = make_float2(W1s[i], W1v[i]);
    for (int i = tid; i < 4096; i += 256) sWsc[i] = make_float2(Wscs[i], Wscv[i]);
    __syncthreads();

    const int warp = tid >> 5, lane = tid & 31;
    const int nwarps = gridDim.x * 8;
    const float l1n = 0.17677669529663687f;  // 1/sqrt(32)
    const float scn = 0.08838834764831843f;  // 1/sqrt(32*4)
    const float4 z4 = make_float4(0.f, 0.f, 0.f, 0.f);

    for (int n = blockIdx.x * 8 + warp; n < NN; n += nwarps) {
        sRaw4[warp][lane] = __ldg((const float4*)(nf + (size_t)n * 128) + lane);
        g_midA[n * 32 + lane] = z4;
        g_midB[n * 32 + lane] = z4;
        if (lane == 0) g_count[n] = 0;
        __syncwarp();
        {
            const float* raw = (const float*)sRaw4[warp];
            sRow[warp][lane] = make_float4(raw[lane],
                                           raw[32 + lane * 3 + 0],
                                           raw[32 + lane * 3 + 1],
                                           raw[32 + lane * 3 + 2]);
        }
        __syncwarp();

        int sp = 0;
#pragma unroll
        for (int v = 0; v < 4; v++)
            if (nattr[n * 4 + v] > 0.5f) sp = v;

        const int w = lane;
        float ys = 0.f, yv0 = 0.f, yv1 = 0.f, yv2 = 0.f;
        float ss = 0.f, sv0 = 0.f, sv1 = 0.f, sv2 = 0.f;
        const float2* wsc = sWsc + sp * 32 + w;
#pragma unroll 8
        for (int u = 0; u < 32; u++) {
            float4 x = sRow[warp][u];
            float2 ab = sW1[u * 32 + w];
            ys  = fmaf(x.x, ab.x, ys);
            yv0 = fmaf(x.y, ab.y, yv0);
            yv1 = fmaf(x.z, ab.y, yv1);
            yv2 = fmaf(x.w, ab.y, yv2);
            float2 cd = wsc[u * 128];
            ss  = fmaf(x.x, cd.x, ss);
            sv0 = fmaf(x.y, cd.y, sv0);
            sv1 = fmaf(x.z, cd.y, sv1);
            sv2 = fmaf(x.w, cd.y, sv2);
        }

        g_y[n * 32 + w] = make_float4(ys * l1n, yv0 * l1n, yv1 * l1n, yv2 * l1n);

        float* orow = out + (size_t)n * 128;
        orow[w] = ss * scn;
        orow[32 + w * 3 + 0] = sv0 * scn;
        orow[32 + w * 3 + 1] = sv1 * scn;
        orow[32 + w * 3 + 2] = sv2 * scn;
        __syncwarp();
    }
}

// ---------------------------------------------------------------------------
// Kernel 2: dst-degree histogram.
// ---------------------------------------------------------------------------
__global__ void hist_kernel(const int* __restrict__ ei) {
    const int stride = gridDim.x * blockDim.x;
    for (int e = blockIdx.x * blockDim.x + threadIdx.x; e < NE; e += stride)
        atomicAdd(&g_count[__ldg(ei + NE + e)], 1);
}

// ---------------------------------------------------------------------------
// Kernels 3a/3b/3c: exclusive prefix scan of g_count -> g_start, g_cursor.
// ---------------------------------------------------------------------------
__global__ void scan1_kernel() {
    __shared__ int sh[1024];
    const int i = blockIdx.x * 1024 + threadIdx.x;
    const int v = (i < NN) ? g_count[i] : 0;
    sh[threadIdx.x] = v;
    __syncthreads();
#pragma unroll
    for (int off = 1; off < 1024; off <<= 1) {
        int t = (threadIdx.x >= off) ? sh[threadIdx.x - off] : 0;
        __syncthreads();
        sh[threadIdx.x] += t;
        __syncthreads();
    }
    if (i < NN) g_start[i] = sh[threadIdx.x] - v;  // exclusive
    if (threadIdx.x == 1023) g_bsum[blockIdx.x] = sh[1023];
}

__global__ void scan2_kernel() {
    __shared__ int sh[64];
    const int t = threadIdx.x;
    const int v = (t < SCAN_BLOCKS) ? g_bsum[t] : 0;
    sh[t] = v;
    __syncthreads();
#pragma unroll
    for (int off = 1; off < 64; off <<= 1) {
        int x = (t >= off) ? sh[t - off] : 0;
        __syncthreads();
        sh[t] += x;
        __syncthreads();
    }
    if (t < SCAN_BLOCKS) g_bsum[t] = sh[t] - v;
}

__global__ void scan3_kernel() {
    const int i = blockIdx.x * 1024 + threadIdx.x;
    if (i < NN) {
        int s = g_start[i] + g_bsum[blockIdx.x];
        g_start[i] = s;
        g_cursor[i] = s;
    }
}

// ---------------------------------------------------------------------------
// Kernel 4: scatter edges into dst-sorted arrays: {src,dst}, edge_attr, eid.
// ---------------------------------------------------------------------------
__global__ void scatter_kernel(const int* __restrict__ ei,
                               const float* __restrict__ ea) {
    const float4* ea4 = (const float4*)ea;
    const int stride = gridDim.x * blockDim.x;
    for (int e = blockIdx.x * blockDim.x + threadIdx.x; e < NE; e += stride) {
        int src = __ldg(ei + e);
        int dst = __ldg(ei + NE + e);
        float4 av = __ldg(ea4 + e);
        int pos = atomicAdd(&g_cursor[dst], 1);
        g_sd[pos]  = make_int2(src, dst);
        g_avs[pos] = av;
        g_eid[pos] = e;
    }
}

// ---------------------------------------------------------------------------
// Kernel 5: h in sorted order. 8 lanes per sorted position (4/warp).
// Gathers eb via eid (32B scattered read), writes g_hs coalesced.
// ---------------------------------------------------------------------------
__global__ void h_sorted_kernel(const float* __restrict__ eb,
                                const float* __restrict__ fw1) {
    const int tid = threadIdx.x;
    const int lane = tid & 31;
    const int g = lane >> 3, j = lane & 7;
    const int gwarp = (blockIdx.x * blockDim.x + tid) >> 5;
    const int nwarps = (gridDim.x * blockDim.x) >> 5;
    const float is8 = 0.3535533905932738f;

    float w1c[8];
#pragma unroll
    for (int k = 0; k < 8; k++) w1c[k] = __ldg(fw1 + k * 8 + j);

    const int ntasks = NE / 4;
    for (int t = gwarp; t < ntasks; t += nwarps) {
        const int pos = t * 4 + g;
        const int e = __ldg(&g_eid[pos]);
        float myeb = __ldg(eb + (size_t)e * 8 + j);

        float acc = 0.f;
#pragma unroll
        for (int k = 0; k < 8; k++)
            acc = fmaf(__shfl_sync(0xffffffffu, myeb, (g << 3) + k), w1c[k], acc);
        acc *= is8;
        float hv = __fdividef(acc, 1.f + __expf(-acc));  // silu

        g_hs[(size_t)pos * 8 + j] = hv;   // coalesced
    }
}

// ---------------------------------------------------------------------------
// Kernel 6: edge-balanced accumulate. Warp per 32-edge sorted chunk.
// All per-edge data loaded coalesced once and staged in smem; inner loop is
// LDS broadcasts + 1 prefetched y gather + register FFMA. Register segment
// accumulation; RED.v4 flush only at dst boundaries (~3 per chunk).
// ---------------------------------------------------------------------------
__global__ void __launch_bounds__(256) edge_accum_kernel(
                              const float* __restrict__ fw2) {
    __shared__ float4 sAv[8][32];
    __shared__ float4 sH[8][64];   // [t*2 + {0,1}]

    const int tid = threadIdx.x;
    const int warp = tid >> 5, lane = tid & 31;
    const int gwarp = blockIdx.x * 8 + warp;
    const int nwarps = gridDim.x * 8;
    const int u = lane;
    const float is8 = 0.3535533905932738f;
    const float IS3 = 0.5773502691896258f;
    const float4* hs4 = (const float4*)g_hs;

    float w2r[32];                            // [j][c], is8 pre-folded
#pragma unroll
    for (int j = 0; j < 8; j++)
#pragma unroll
        for (int c = 0; c < 4; c++)
            w2r[j * 4 + c] = __ldg(fw2 + j * 128 + c * 32 + u) * is8;

    const int nchunks = NE / 32;
    for (int c = gwarp; c < nchunks; c += nwarps) {
        const int base = c * 32;
        const int2 sd = __ldg(&g_sd[base + lane]);     // coalesced
        sAv[warp][lane] = __ldg(&g_avs[base + lane]);  // coalesced
        sH[warp][lane * 2]     = __ldg(hs4 + (size_t)(base + lane) * 2);
        sH[warp][lane * 2 + 1] = __ldg(hs4 + (size_t)(base + lane) * 2 + 1);
        __syncwarp();

        float As = 0.f, Av0 = 0.f, Av1 = 0.f, Av2 = 0.f;
        float Bs = 0.f, Bv0 = 0.f, Bv1 = 0.f, Bv2 = 0.f;

        int dcur = __shfl_sync(0xffffffffu, sd.y, 0);
        int srcn = __shfl_sync(0xffffffffu, sd.x, 0);
        float4 y = __ldg(&g_y[srcn * 32 + u]);

        for (int t = 0; t < 32; t++) {
            const float4 yc = y;
            const int tn = (t + 1) & 31;          // t=31 wraps (dummy reload)
            srcn = __shfl_sync(0xffffffffu, sd.x, tn);
            const int dnext = __shfl_sync(0xffffffffu, sd.y, tn);
            y = __ldg(&g_y[srcn * 32 + u]);       // prefetch next y

            const float4 av  = sAv[warp][t];      // LDS.128 broadcast
            const float4 h0c = sH[warp][t * 2];
            const float4 h1c = sH[warp][t * 2 + 1];

            // MLP layer 2 (register weights)
            float w00, w01, w10, w11;
            w00 = h0c.x * w2r[0];
            w01 = h0c.x * w2r[1];
            w10 = h0c.x * w2r[2];
            w11 = h0c.x * w2r[3];
            w00 = fmaf(h0c.y, w2r[4],  w00); w01 = fmaf(h0c.y, w2r[5],  w01);
            w10 = fmaf(h0c.y, w2r[6],  w10); w11 = fmaf(h0c.y, w2r[7],  w11);
            w00 = fmaf(h0c.z, w2r[8],  w00); w01 = fmaf(h0c.z, w2r[9],  w01);
            w10 = fmaf(h0c.z, w2r[10], w10); w11 = fmaf(h0c.z, w2r[11], w11);
            w00 = fmaf(h0c.w, w2r[12], w00); w01 = fmaf(h0c.w, w2r[13], w01);
            w10 = fmaf(h0c.w, w2r[14], w10); w11 = fmaf(h0c.w, w2r[15], w11);
            w00 = fmaf(h1c.x, w2r[16], w00); w01 = fmaf(h1c.x, w2r[17], w01);
            w10 = fmaf(h1c.x, w2r[18], w10); w11 = fmaf(h1c.x, w2r[19], w11);
            w00 = fmaf(h1c.y, w2r[20], w00); w01 = fmaf(h1c.y, w2r[21], w01);
            w10 = fmaf(h1c.y, w2r[22], w10); w11 = fmaf(h1c.y, w2r[23], w11);
            w00 = fmaf(h1c.z, w2r[24], w00); w01 = fmaf(h1c.z, w2r[25], w01);
            w10 = fmaf(h1c.z, w2r[26], w10); w11 = fmaf(h1c.z, w2r[27], w11);
            w00 = fmaf(h1c.w, w2r[28], w00); w01 = fmaf(h1c.w, w2r[29], w01);
            w10 = fmaf(h1c.w, w2r[30], w10); w11 = fmaf(h1c.w, w2r[31], w11);

            const float es    = yc.x;
            const float dotv  = fmaf(yc.y, av.y, fmaf(yc.z, av.z, yc.w * av.w));
            const float wes   = w01 * es;
            const float w10a0 = w10 * av.x;

            As  += w00 * es * av.x;
            Bs  += w11 * dotv * IS3;
            Av0 = fmaf(wes, av.y, Av0);
            Av1 = fmaf(wes, av.z, Av1);
            Av2 = fmaf(wes, av.w, Av2);
            Bv0 = fmaf(w10a0, yc.y, Bv0);
            Bv1 = fmaf(w10a0, yc.z, Bv1);
            Bv2 = fmaf(w10a0, yc.w, Bv2);

            // flush at segment boundary (warp-uniform, ~3 per chunk)
            if (t == 31 || dnext != dcur) {
                red_add_f4(&g_midA[dcur * 32 + u], make_float4(As, Av0, Av1, Av2));
                red_add_f4(&g_midB[dcur * 32 + u], make_float4(Bs, Bv0, Bv1, Bv2));
                As = 0.f; Av0 = 0.f; Av1 = 0.f; Av2 = 0.f;
                Bs = 0.f; Bv0 = 0.f; Bv1 = 0.f; Bv2 = 0.f;
            }
            dcur = dnext;
        }
        __syncwarp();
    }
}

// ---------------------------------------------------------------------------
// Kernel 7: per-node output. out += lin2(mid) (sc already in out).
// ---------------------------------------------------------------------------
__global__ void node_out_kernel(const float* __restrict__ W2s,
                                const float* __restrict__ W2v,
                                float* __restrict__ out) {
    __shared__ float2 sW2[2048];
    __shared__ float4 sMid[8][64];

    const int tid = threadIdx.x;
    for (int i = tid; i < 2048; i += 256) sW2[i] = make_float2(W2s[i], W2v[i]);
    __syncthreads();

    const int warp = tid >> 5, lane = tid & 31;
    const int nwarps = gridDim.x * 8;
    const float cc = 0.25f * 0.125f;  // 1/sqrt(16) * 1/sqrt(64)

    for (int n = blockIdx.x * 8 + warp; n < NN; n += nwarps) {
        sMid[warp][lane]      = g_midA[n * 32 + lane];
        sMid[warp][32 + lane] = g_midB[n * 32 + lane];
        __syncwarp();

        const int w = lane;
        float os = 0.f, ov0 = 0.f, ov1 = 0.f, ov2 = 0.f;
#pragma unroll 16
        for (int uu = 0; uu < 64; uu++) {
            float4 mm = sMid[warp][uu];
            float2 ab = sW2[uu * 32 + w];
            os  = fmaf(mm.x, ab.x, os);
            ov0 = fmaf(mm.y, ab.y, ov0);
            ov1 = fmaf(mm.z, ab.y, ov1);
            ov2 = fmaf(mm.w, ab.y, ov2);
        }

        float* orow = out + (size_t)n * 128;
        orow[w]              += os  * cc;
        orow[32 + w * 3 + 0] += ov0 * cc;
        orow[32 + w * 3 + 1] += ov1 * cc;
        orow[32 + w * 3 + 2] += ov2 * cc;
        __syncwarp();
    }
}

// ---------------------------------------------------------------------------
extern "C" void kernel_launch(void* const* d_in, const int* in_sizes, int n_in,
                              void* d_out, int out_size) {
    const float* nf    = (const float*)d_in[0];
    const float* nattr = (const float*)d_in[1];
    const float* eb    = (const float*)d_in[2];
    const float* ea    = (const float*)d_in[3];
    const int*   ei    = (const int*)d_in[4];
    const float* W1s   = (const float*)d_in[5];
    const float* W1v   = (const float*)d_in[6];
    const float* fw1   = (const float*)d_in[7];
    const float* fw2   = (const float*)d_in[8];
    const float* W2s   = (const float*)d_in[9];
    const float* W2v   = (const float*)d_in[10];
    const float* Wscs  = (const float*)d_in[11];
    const float* Wscv  = (const float*)d_in[12];
    float* out = (float*)d_out;

    node_prep_kernel<<<1184, 256>>>(nf, nattr, W1s, W1v, Wscs, Wscv, out);
    hist_kernel<<<1184, 256>>>(ei);
    scan1_kernel<<<SCAN_BLOCKS, 1024>>>();
    scan2_kernel<<<1, 64>>>();
    scan3_kernel<<<SCAN_BLOCKS, 1024>>>();
    scatter_kernel<<<1184, 256>>>(ei, ea);
    h_sorted_kernel<<<1184, 256>>>(eb, fw1);
    edge_accum_kernel<<<1184, 256>>>(fw2);
    node_out_kernel<<<1184, 256>>>(W2s, W2v, out);
}

// round 12
// speedup vs baseline: 1.1318x; 1.1318x over previous
#include <cuda_runtime.h>
#include <cuda_bf16.h>

#define NN 50000
#define NE 800000

// Scratch: __device__ globals (no allocation allowed).
// g_y[n*32+u]    = {ys[u], yv[u][0..2]}   (post-lin1, scaled)
// g_midA/B[n*32+u] = segment sums of edge outputs (A: o_s_a/o_v_a, B: o_s_b/o_v_b)
__device__ float4 g_y[NN * 32];
__device__ float4 g_midA[NN * 32];
__device__ float4 g_midB[NN * 32];

__device__ __forceinline__ void red_add_f4(float4* p, float4 v) {
    asm volatile("red.global.add.v4.f32 [%0], {%1, %2, %3, %4};"
                 :: "l"(p), "f"(v.x), "f"(v.y), "f"(v.z), "f"(v.w)
                 : "memory");
}

// ---------------------------------------------------------------------------
// Kernel 1: per-node prep + zero mid accumulators.
//   ys/yv = lin1(x) ; sc_s/sc_v (self-connection) written directly into out.
// Warp per node, lane = output channel w.
// Node row loaded with ONE coalesced LDG.128 per lane (512B/warp exact, no
// stride-3 sector over-fetch), repacked through smem, then consumed as
// LDS.128 broadcasts.
// ---------------------------------------------------------------------------
__global__ void node_prep_kernel(const float* __restrict__ nf,
                                 const float* __restrict__ nattr,
                                 const float* __restrict__ W1s,
                                 const float* __restrict__ W1v,
                                 const float* __restrict__ Wscs,
                                 const float* __restrict__ Wscv,
                                 float* __restrict__ out) {
    __shared__ float2 sW1[1024];    // [u][w] -> {W1s, W1v}
    __shared__ float2 sWsc[4096];   // [u][sp][w] -> {Wscs, Wscv}
    __shared__ float4 sRaw4[8][32]; // raw row, coalesced
    __shared__ float4 sRow[8][32];  // packed {xs, xv0, xv1, xv2} per u

    const int tid = threadIdx.x;
    for (int i = tid; i < 1024; i += 256) sW1[i] = make_float2(W1s[i], W1v[i]);
    for (int i = tid; i < 4096; i += 256) sWsc[i] = make_float2(Wscs[i], Wscv[i]);
    __syncthreads();

    const int warp = tid >> 5, lane = tid & 31;
    const int nwarps = gridDim.x * 8;
    const float l1n = 0.17677669529663687f;  // 1/sqrt(32)
    const float scn = 0.08838834764831843f;  // 1/sqrt(32*4)
    const float4 z4 = make_float4(0.f, 0.f, 0.f, 0.f);

    for (int n = blockIdx.x * 8 + warp; n < NN; n += nwarps) {
        // coalesced row load: 32 lanes x float4 = 512B = whole row
        sRaw4[warp][lane] = __ldg((const float4*)(nf + (size_t)n * 128) + lane);
        // zero the mid accumulators for this node
        g_midA[n * 32 + lane] = z4;
        g_midB[n * 32 + lane] = z4;
        __syncwarp();
        {
            const float* raw = (const float*)sRaw4[warp];
            sRow[warp][lane] = make_float4(raw[lane],
                                           raw[32 + lane * 3 + 0],
                                           raw[32 + lane * 3 + 1],
                                           raw[32 + lane * 3 + 2]);
        }
        __syncwarp();

        int sp = 0;
#pragma unroll
        for (int v = 0; v < 4; v++)
            if (nattr[n * 4 + v] > 0.5f) sp = v;

        const int w = lane;
        float ys = 0.f, yv0 = 0.f, yv1 = 0.f, yv2 = 0.f;
        float ss = 0.f, sv0 = 0.f, sv1 = 0.f, sv2 = 0.f;
        const float2* wsc = sWsc + sp * 32 + w;
#pragma unroll 8
        for (int u = 0; u < 32; u++) {
            float4 x = sRow[warp][u];            // 1 LDS.128 broadcast
            float2 ab = sW1[u * 32 + w];
            ys  = fmaf(x.x, ab.x, ys);
            yv0 = fmaf(x.y, ab.y, yv0);
            yv1 = fmaf(x.z, ab.y, yv1);
            yv2 = fmaf(x.w, ab.y, yv2);
            float2 cd = wsc[u * 128];
            ss  = fmaf(x.x, cd.x, ss);
            sv0 = fmaf(x.y, cd.y, sv0);
            sv1 = fmaf(x.z, cd.y, sv1);
            sv2 = fmaf(x.w, cd.y, sv2);
        }

        g_y[n * 32 + w] = make_float4(ys * l1n, yv0 * l1n, yv1 * l1n, yv2 * l1n);

        float* orow = out + (size_t)n * 128;
        orow[w] = ss * scn;
        orow[32 + w * 3 + 0] = sv0 * scn;
        orow[32 + w * 3 + 1] = sv1 * scn;
        orow[32 + w * 3 + 2] = sv2 * scn;
        __syncwarp();
    }
}

// ---------------------------------------------------------------------------
// Kernel 2: edge kernel. Warp per edge, lane = channel u.
// ALL weights live in registers:
//   w1r[k]    = fc_w1[k][lane&7]          (8 regs, first MLP layer)
//   w2r[j][c] = fc_w2[j][c*32 + lane]     (32 regs, second MLP layer)
// No shared memory, no per-edge LDS. h computed cooperatively (lanes 0-7
// via shfl), 2 MUFU warp-ops per edge for silu. Outputs scattered with
// 2 x red.global.add.v4 per lane (LTS-bound — near the L2 RMW ceiling).
// ---------------------------------------------------------------------------
__global__ void __launch_bounds__(256) edge_kernel(
                            const float* __restrict__ eb,
                            const float* __restrict__ ea,
                            const int* __restrict__ ei,
                            const float* __restrict__ fw1,
                            const float* __restrict__ fw2) {
    const int tid = threadIdx.x;
    const int warp = tid >> 5, lane = tid & 31;
    const int nwarps = gridDim.x * 8;
    const float is8 = 0.3535533905932738f;  // 1/sqrt(8)
    const float IS3 = 0.5773502691896258f;  // 1/sqrt(3)
    const int u = lane;

    // loop-invariant weight preload into registers
    float w1r[8];
#pragma unroll
    for (int k = 0; k < 8; k++) w1r[k] = __ldg(fw1 + k * 8 + (lane & 7));
    float w2r[32];
#pragma unroll
    for (int j = 0; j < 8; j++)
#pragma unroll
        for (int c = 0; c < 4; c++)
            w2r[j * 4 + c] = __ldg(fw2 + j * 128 + c * 32 + u);

    for (int e = blockIdx.x * 8 + warp; e < NE; e += nwarps) {
        const int src = __ldg(ei + e);
        const int dst = __ldg(ei + NE + e);

        // issue long-latency loads early
        const float4 y  = __ldg(&g_y[src * 32 + u]);                   // gather (L2-resident)
        const float4 av = __ldg((const float4*)(ea + (size_t)e * 4));  // 1 broadcast LDG.128
        float ebv = (lane < 8) ? __ldg(eb + (size_t)e * 8 + lane) : 0.f;

        // cooperative MLP layer 1: lane j (mod 8) computes h[j]
        float acc = 0.f;
#pragma unroll
        for (int k = 0; k < 8; k++)
            acc = fmaf(__shfl_sync(0xffffffffu, ebv, k), w1r[k], acc);
        acc *= is8;
        float hv = __fdividef(acc, 1.f + __expf(-acc));   // silu, 2 MUFU/warp

        // layer 2: pure register FFMA
        float w00 = 0.f, w01 = 0.f, w10 = 0.f, w11 = 0.f;
#pragma unroll
        for (int j = 0; j < 8; j++) {
            const float hj = __shfl_sync(0xffffffffu, hv, j);
            w00 = fmaf(hj, w2r[j * 4 + 0], w00);
            w01 = fmaf(hj, w2r[j * 4 + 1], w01);
            w10 = fmaf(hj, w2r[j * 4 + 2], w10);
            w11 = fmaf(hj, w2r[j * 4 + 3], w11);
        }
        w00 *= is8; w01 *= is8; w10 *= is8; w11 *= is8;

        const float es    = y.x;
        const float osa   = w00 * es * av.x;
        const float dotv  = fmaf(y.y, av.y, fmaf(y.z, av.z, y.w * av.w));
        const float osb   = w11 * dotv * IS3;
        const float wes   = w01 * es;
        const float w10a0 = w10 * av.x;

        float4 A = make_float4(osa, wes * av.y, wes * av.z, wes * av.w);
        float4 B = make_float4(osb, w10a0 * y.y, w10a0 * y.z, w10a0 * y.w);

        red_add_f4(&g_midA[dst * 32 + u], A);
        red_add_f4(&g_midB[dst * 32 + u], B);
    }
}

// ---------------------------------------------------------------------------
// Kernel 3: per-node output.
//   out_s += (mid_s @ W_lin2_s) * inv * l2n ; out_v likewise (sc already in out)
// Warp per node, lane = output channel w.
// ---------------------------------------------------------------------------
__global__ void node_out_kernel(const float* __restrict__ W2s,
                                const float* __restrict__ W2v,
                                float* __restrict__ out) {
    __shared__ float2 sW2[2048];   // [u][w] -> {W2s, W2v}, u in [0,64)
    __shared__ float4 sMid[8][64];

    const int tid = threadIdx.x;
    for (int i = tid; i < 2048; i += 256) sW2[i] = make_float2(W2s[i], W2v[i]);
    __syncthreads();

    const int warp = tid >> 5, lane = tid & 31;
    const int nwarps = gridDim.x * 8;
    const float c = 0.25f * 0.125f;  // 1/sqrt(16) * 1/sqrt(64)

    for (int n = blockIdx.x * 8 + warp; n < NN; n += nwarps) {
        sMid[warp][lane]      = g_midA[n * 32 + lane];
        sMid[warp][32 + lane] = g_midB[n * 32 + lane];
        __syncwarp();

        const int w = lane;
        float os = 0.f, ov0 = 0.f, ov1 = 0.f, ov2 = 0.f;
#pragma unroll 16
        for (int uu = 0; uu < 64; uu++) {
            float4 m  = sMid[warp][uu];
            float2 ab = sW2[uu * 32 + w];
            os  = fmaf(m.x, ab.x, os);
            ov0 = fmaf(m.y, ab.y, ov0);
            ov1 = fmaf(m.z, ab.y, ov1);
            ov2 = fmaf(m.w, ab.y, ov2);
        }

        float* orow = out + (size_t)n * 128;
        orow[w]              += os  * c;
        orow[32 + w * 3 + 0] += ov0 * c;
        orow[32 + w * 3 + 1] += ov1 * c;
        orow[32 + w * 3 + 2] += ov2 * c;
        __syncwarp();
    }
}

// ---------------------------------------------------------------------------
extern "C" void kernel_launch(void* const* d_in, const int* in_sizes, int n_in,
                              void* d_out, int out_size) {
    const float* nf    = (const float*)d_in[0];   // node_features (N, 128)
    const float* nattr = (const float*)d_in[1];   // node_attr (N, 4)
    const float* eb    = (const float*)d_in[2];   // edge_embedding (E, 8)
    const float* ea    = (const float*)d_in[3];   // edge_attr (E, 4)
    const int*   ei    = (const int*)d_in[4];     // edge_index (2, E)
    const float* W1s   = (const float*)d_in[5];
    const float* W1v   = (const float*)d_in[6];
    const float* fw1   = (const float*)d_in[7];
    const float* fw2   = (const float*)d_in[8];
    const float* W2s   = (const float*)d_in[9];
    const float* W2v   = (const float*)d_in[10];
    const float* Wscs  = (const float*)d_in[11];
    const float* Wscv  = (const float*)d_in[12];
    float* out = (float*)d_out;

    node_prep_kernel<<<1184, 256>>>(nf, nattr, W1s, W1v, Wscs, Wscv, out);
    edge_kernel<<<1184, 256>>>(eb, ea, ei, fw1, fw2);
    node_out_kernel<<<1184, 256>>>(W2s, W2v, out);
}

// round 13
// speedup vs baseline: 1.2050x; 1.0647x over previous
#include <cuda_runtime.h>
#include <cuda_bf16.h>

#define NN 50000
#define NE 800000

// Scratch: __device__ globals (no allocation allowed).
__device__ float4 g_y[NN * 32];
__device__ float4 g_midA[NN * 32];
__device__ float4 g_midB[NN * 32];

__device__ __forceinline__ void red_add_f4(float4* p, float4 v) {
    asm volatile("red.global.add.v4.f32 [%0], {%1, %2, %3, %4};"
                 :: "l"(p), "f"(v.x), "f"(v.y), "f"(v.z), "f"(v.w)
                 : "memory");
}

// ---------------------------------------------------------------------------
// Kernel 1: per-node prep + zero mid accumulators. TWO nodes per warp so the
// sW1 weight LDS (the dominant crossbar cost) is amortized across 2 nodes.
// In-place repack buffer keeps static smem at exactly 48KB.
// ---------------------------------------------------------------------------
__global__ void node_prep_kernel(const float* __restrict__ nf,
                                 const float* __restrict__ nattr,
                                 const float* __restrict__ W1s,
                                 const float* __restrict__ W1v,
                                 const float* __restrict__ Wscs,
                                 const float* __restrict__ Wscv,
                                 float* __restrict__ out) {
    __shared__ float2 sW1[1024];      // [u][w] -> {W1s, W1v}            8KB
    __shared__ float2 sWsc[4096];     // [u][sp][w] -> {Wscs, Wscv}     32KB
    __shared__ float4 sBuf[8][2][32]; // per-warp, 2 nodes, repacked row  8KB

    const int tid = threadIdx.x;
    for (int i = tid; i < 1024; i += 256) sW1[i] = make_float2(W1s[i], W1v[i]);
    for (int i = tid; i < 4096; i += 256) sWsc[i] = make_float2(Wscs[i], Wscv[i]);
    __syncthreads();

    const int warp = tid >> 5, lane = tid & 31;
    const int nwarps = gridDim.x * 8;
    const float l1n = 0.17677669529663687f;  // 1/sqrt(32)
    const float scn = 0.08838834764831843f;  // 1/sqrt(32*4)
    const float4 z4 = make_float4(0.f, 0.f, 0.f, 0.f);

    for (int n0 = (blockIdx.x * 8 + warp) * 2; n0 < NN; n0 += nwarps * 2) {
        const int n1 = n0 + 1;   // NN even, n0 always even -> n1 < NN

        // coalesced row loads (512B/warp per node) + mid zeroing
        sBuf[warp][0][lane] = __ldg((const float4*)(nf + (size_t)n0 * 128) + lane);
        sBuf[warp][1][lane] = __ldg((const float4*)(nf + (size_t)n1 * 128) + lane);
        g_midA[n0 * 32 + lane] = z4;
        g_midB[n0 * 32 + lane] = z4;
        g_midA[n1 * 32 + lane] = z4;
        g_midB[n1 * 32 + lane] = z4;
        __syncwarp();

        // in-place repack: raw -> {xs, xv0, xv1, xv2}
        const float* r0 = (const float*)sBuf[warp][0];
        const float* r1 = (const float*)sBuf[warp][1];
        float a_s = r0[lane], a0 = r0[32 + lane * 3 + 0],
              a1 = r0[32 + lane * 3 + 1], a2 = r0[32 + lane * 3 + 2];
        float b_s = r1[lane], b0 = r1[32 + lane * 3 + 0],
              b1 = r1[32 + lane * 3 + 1], b2 = r1[32 + lane * 3 + 2];
        __syncwarp();
        sBuf[warp][0][lane] = make_float4(a_s, a0, a1, a2);
        sBuf[warp][1][lane] = make_float4(b_s, b0, b1, b2);
        __syncwarp();

        int sp0 = 0, sp1 = 0;
#pragma unroll
        for (int v = 0; v < 4; v++) {
            if (nattr[n0 * 4 + v] > 0.5f) sp0 = v;
            if (nattr[n1 * 4 + v] > 0.5f) sp1 = v;
        }

        const int w = lane;
        float ysA = 0.f, y0A = 0.f, y1A = 0.f, y2A = 0.f;
        float ssA = 0.f, s0A = 0.f, s1A = 0.f, s2A = 0.f;
        float ysB = 0.f, y0B = 0.f, y1B = 0.f, y2B = 0.f;
        float ssB = 0.f, s0B = 0.f, s1B = 0.f, s2B = 0.f;
        const float2* wscA = sWsc + sp0 * 32 + w;
        const float2* wscB = sWsc + sp1 * 32 + w;
#pragma unroll 8
        for (int u = 0; u < 32; u++) {
            float4 xa = sBuf[warp][0][u];        // LDS.128 broadcast
            float4 xb = sBuf[warp][1][u];
            float2 ab = sW1[u * 32 + w];         // shared across both nodes
            ysA = fmaf(xa.x, ab.x, ysA);  ysB = fmaf(xb.x, ab.x, ysB);
            y0A = fmaf(xa.y, ab.y, y0A);  y0B = fmaf(xb.y, ab.y, y0B);
            y1A = fmaf(xa.z, ab.y, y1A);  y1B = fmaf(xb.z, ab.y, y1B);
            y2A = fmaf(xa.w, ab.y, y2A);  y2B = fmaf(xb.w, ab.y, y2B);
            float2 ca = wscA[u * 128];
            float2 cb = wscB[u * 128];
            ssA = fmaf(xa.x, ca.x, ssA);  ssB = fmaf(xb.x, cb.x, ssB);
            s0A = fmaf(xa.y, ca.y, s0A);  s0B = fmaf(xb.y, cb.y, s0B);
            s1A = fmaf(xa.z, ca.y, s1A);  s1B = fmaf(xb.z, cb.y, s1B);
            s2A = fmaf(xa.w, ca.y, s2A);  s2B = fmaf(xb.w, cb.y, s2B);
        }

        g_y[n0 * 32 + w] = make_float4(ysA * l1n, y0A * l1n, y1A * l1n, y2A * l1n);
        g_y[n1 * 32 + w] = make_float4(ysB * l1n, y0B * l1n, y1B * l1n, y2B * l1n);

        float* o0 = out + (size_t)n0 * 128;
        o0[w] = ssA * scn;
        o0[32 + w * 3 + 0] = s0A * scn;
        o0[32 + w * 3 + 1] = s1A * scn;
        o0[32 + w * 3 + 2] = s2A * scn;
        float* o1 = out + (size_t)n1 * 128;
        o1[w] = ssB * scn;
        o1[32 + w * 3 + 0] = s0B * scn;
        o1[32 + w * 3 + 1] = s1B * scn;
        o1[32 + w * 3 + 2] = s2B * scn;
        __syncwarp();
    }
}

// ---------------------------------------------------------------------------
// Kernel 2: edge kernel (unchanged from best-known). Warp per edge,
// lane = channel u, all MLP weights register-resident, cooperative silu,
// 2 x red.global.add.v4 per lane (LTS-bound).
// ---------------------------------------------------------------------------
__global__ void __launch_bounds__(256) edge_kernel(
                            const float* __restrict__ eb,
                            const float* __restrict__ ea,
                            const int* __restrict__ ei,
                            const float* __restrict__ fw1,
                            const float* __restrict__ fw2) {
    const int tid = threadIdx.x;
    const int warp = tid >> 5, lane = tid & 31;
    const int nwarps = gridDim.x * 8;
    const float is8 = 0.3535533905932738f;  // 1/sqrt(8)
    const float IS3 = 0.5773502691896258f;  // 1/sqrt(3)
    const int u = lane;

    float w1r[8];
#pragma unroll
    for (int k = 0; k < 8; k++) w1r[k] = __ldg(fw1 + k * 8 + (lane & 7));
    float w2r[32];
#pragma unroll
    for (int j = 0; j < 8; j++)
#pragma unroll
        for (int c = 0; c < 4; c++)
            w2r[j * 4 + c] = __ldg(fw2 + j * 128 + c * 32 + u);

    for (int e = blockIdx.x * 8 + warp; e < NE; e += nwarps) {
        const int src = __ldg(ei + e);
        const int dst = __ldg(ei + NE + e);

        const float4 y  = __ldg(&g_y[src * 32 + u]);
        const float4 av = __ldg((const float4*)(ea + (size_t)e * 4));
        float ebv = (lane < 8) ? __ldg(eb + (size_t)e * 8 + lane) : 0.f;

        float acc = 0.f;
#pragma unroll
        for (int k = 0; k < 8; k++)
            acc = fmaf(__shfl_sync(0xffffffffu, ebv, k), w1r[k], acc);
        acc *= is8;
        float hv = __fdividef(acc, 1.f + __expf(-acc));   // silu

        float w00 = 0.f, w01 = 0.f, w10 = 0.f, w11 = 0.f;
#pragma unroll
        for (int j = 0; j < 8; j++) {
            const float hj = __shfl_sync(0xffffffffu, hv, j);
            w00 = fmaf(hj, w2r[j * 4 + 0], w00);
            w01 = fmaf(hj, w2r[j * 4 + 1], w01);
            w10 = fmaf(hj, w2r[j * 4 + 2], w10);
            w11 = fmaf(hj, w2r[j * 4 + 3], w11);
        }
        w00 *= is8; w01 *= is8; w10 *= is8; w11 *= is8;

        const float es    = y.x;
        const float osa   = w00 * es * av.x;
        const float dotv  = fmaf(y.y, av.y, fmaf(y.z, av.z, y.w * av.w));
        const float osb   = w11 * dotv * IS3;
        const float wes   = w01 * es;
        const float w10a0 = w10 * av.x;

        float4 A = make_float4(osa, wes * av.y, wes * av.z, wes * av.w);
        float4 B = make_float4(osb, w10a0 * y.y, w10a0 * y.z, w10a0 * y.w);

        red_add_f4(&g_midA[dst * 32 + u], A);
        red_add_f4(&g_midB[dst * 32 + u], B);
    }
}

// ---------------------------------------------------------------------------
// Kernel 3: per-node output, TWO nodes per warp (sW2 LDS amortized).
//   out += lin2(mid) * inv * l2n (sc already in out).
// ---------------------------------------------------------------------------
__global__ void node_out_kernel(const float* __restrict__ W2s,
                                const float* __restrict__ W2v,
                                float* __restrict__ out) {
    __shared__ float2 sW2[2048];      // [u][w] -> {W2s, W2v}        16KB
    __shared__ float4 sMid[8][128];   // 2 nodes x 64 per warp        16KB

    const int tid = threadIdx.x;
    for (int i = tid; i < 2048; i += 256) sW2[i] = make_float2(W2s[i], W2v[i]);
    __syncthreads();

    const int warp = tid >> 5, lane = tid & 31;
    const int nwarps = gridDim.x * 8;
    const float c = 0.25f * 0.125f;  // 1/sqrt(16) * 1/sqrt(64)

    for (int n0 = (blockIdx.x * 8 + warp) * 2; n0 < NN; n0 += nwarps * 2) {
        const int n1 = n0 + 1;

        sMid[warp][lane]       = g_midA[n0 * 32 + lane];
        sMid[warp][32 + lane]  = g_midB[n0 * 32 + lane];
        sMid[warp][64 + lane]  = g_midA[n1 * 32 + lane];
        sMid[warp][96 + lane]  = g_midB[n1 * 32 + lane];
        __syncwarp();

        const int w = lane;
        float osA = 0.f, v0A = 0.f, v1A = 0.f, v2A = 0.f;
        float osB = 0.f, v0B = 0.f, v1B = 0.f, v2B = 0.f;
#pragma unroll 16
        for (int uu = 0; uu < 64; uu++) {
            float4 ma = sMid[warp][uu];
            float4 mb = sMid[warp][64 + uu];
            float2 ab = sW2[uu * 32 + w];       // shared across both nodes
            osA = fmaf(ma.x, ab.x, osA);  osB = fmaf(mb.x, ab.x, osB);
            v0A = fmaf(ma.y, ab.y, v0A);  v0B = fmaf(mb.y, ab.y, v0B);
            v1A = fmaf(ma.z, ab.y, v1A);  v1B = fmaf(mb.z, ab.y, v1B);
            v2A = fmaf(ma.w, ab.y, v2A);  v2B = fmaf(mb.w, ab.y, v2B);
        }

        float* o0 = out + (size_t)n0 * 128;
        o0[w]              += osA * c;
        o0[32 + w * 3 + 0] += v0A * c;
        o0[32 + w * 3 + 1] += v1A * c;
        o0[32 + w * 3 + 2] += v2A * c;
        float* o1 = out + (size_t)n1 * 128;
        o1[w]              += osB * c;
        o1[32 + w * 3 + 0] += v0B * c;
        o1[32 + w * 3 + 1] += v1B * c;
        o1[32 + w * 3 + 2] += v2B * c;
        __syncwarp();
    }
}

// ---------------------------------------------------------------------------
extern "C" void kernel_launch(void* const* d_in, const int* in_sizes, int n_in,
                              void* d_out, int out_size) {
    const float* nf    = (const float*)d_in[0];
    const float* nattr = (const float*)d_in[1];
    const float* eb    = (const float*)d_in[2];
    const float* ea    = (const float*)d_in[3];
    const int*   ei    = (const int*)d_in[4];
    const float* W1s   = (const float*)d_in[5];
    const float* W1v   = (const float*)d_in[6];
    const float* fw1   = (const float*)d_in[7];
    const float* fw2   = (const float*)d_in[8];
    const float* W2s   = (const float*)d_in[9];
    const float* W2v   = (const float*)d_in[10];
    const float* Wscs  = (const float*)d_in[11];
    const float* Wscv  = (const float*)d_in[12];
    float* out = (float*)d_out;

    node_prep_kernel<<<1184, 256>>>(nf, nattr, W1s, W1v, Wscs, Wscv, out);
    edge_kernel<<<1184, 256>>>(eb, ea, ei, fw1, fw2);
    node_out_kernel<<<1184, 256>>>(W2s, W2v, out);
}

// round 15
// speedup vs baseline: 1.2358x; 1.0255x over previous
#include <cuda_runtime.h>
#include <cuda_bf16.h>
#include <cstdint>

#define NN 50000
#define NE 800000

// Scratch: __device__ globals (no allocation allowed).
// g_y[n*32+u] = {ys, yv0..2} post-lin1.
// g_mid[n*64 + 2u] = A_u {o_s_a, o_v_a}, g_mid[n*64 + 2u+1] = B_u {o_s_b, o_v_b}.
// Interleaved so one edge's whole contribution is a contiguous 1KB block
// (target of one cp.reduce.async.bulk).
__device__ float4 g_y[NN * 32];
__device__ float4 g_mid[NN * 64];

// ---------------------------------------------------------------------------
// Kernel 1: per-node prep + zero mid accumulators. TWO nodes per warp
// (weight-LDS amortized). Unchanged from R13 except mid layout.
// ---------------------------------------------------------------------------
__global__ void node_prep_kernel(const float* __restrict__ nf,
                                 const float* __restrict__ nattr,
                                 const float* __restrict__ W1s,
                                 const float* __restrict__ W1v,
                                 const float* __restrict__ Wscs,
                                 const float* __restrict__ Wscv,
                                 float* __restrict__ out) {
    __shared__ float2 sW1[1024];      // [u][w] -> {W1s, W1v}            8KB
    __shared__ float2 sWsc[4096];     // [u][sp][w] -> {Wscs, Wscv}     32KB
    __shared__ float4 sBuf[8][2][32]; // per-warp, 2 nodes, repacked row  8KB

    const int tid = threadIdx.x;
    for (int i = tid; i < 1024; i += 256) sW1[i] = make_float2(W1s[i], W1v[i]);
    for (int i = tid; i < 4096; i += 256) sWsc[i] = make_float2(Wscs[i], Wscv[i]);
    __syncthreads();

    const int warp = tid >> 5, lane = tid & 31;
    const int nwarps = gridDim.x * 8;
    const float l1n = 0.17677669529663687f;  // 1/sqrt(32)
    const float scn = 0.08838834764831843f;  // 1/sqrt(32*4)
    const float4 z4 = make_float4(0.f, 0.f, 0.f, 0.f);

    for (int n0 = (blockIdx.x * 8 + warp) * 2; n0 < NN; n0 += nwarps * 2) {
        const int n1 = n0 + 1;   // NN even

        sBuf[warp][0][lane] = __ldg((const float4*)(nf + (size_t)n0 * 128) + lane);
        sBuf[warp][1][lane] = __ldg((const float4*)(nf + (size_t)n1 * 128) + lane);
        g_mid[n0 * 64 + lane]      = z4;
        g_mid[n0 * 64 + 32 + lane] = z4;
        g_mid[n1 * 64 + lane]      = z4;
        g_mid[n1 * 64 + 32 + lane] = z4;
        __syncwarp();

        const float* r0 = (const float*)sBuf[warp][0];
        const float* r1 = (const float*)sBuf[warp][1];
        float a_s = r0[lane], a0 = r0[32 + lane * 3 + 0],
              a1 = r0[32 + lane * 3 + 1], a2 = r0[32 + lane * 3 + 2];
        float b_s = r1[lane], b0 = r1[32 + lane * 3 + 0],
              b1 = r1[32 + lane * 3 + 1], b2 = r1[32 + lane * 3 + 2];
        __syncwarp();
        sBuf[warp][0][lane] = make_float4(a_s, a0, a1, a2);
        sBuf[warp][1][lane] = make_float4(b_s, b0, b1, b2);
        __syncwarp();

        int sp0 = 0, sp1 = 0;
#pragma unroll
        for (int v = 0; v < 4; v++) {
            if (nattr[n0 * 4 + v] > 0.5f) sp0 = v;
            if (nattr[n1 * 4 + v] > 0.5f) sp1 = v;
        }

        const int w = lane;
        float ysA = 0.f, y0A = 0.f, y1A = 0.f, y2A = 0.f;
        float ssA = 0.f, s0A = 0.f, s1A = 0.f, s2A = 0.f;
        float ysB = 0.f, y0B = 0.f, y1B = 0.f, y2B = 0.f;
        float ssB = 0.f, s0B = 0.f, s1B = 0.f, s2B = 0.f;
        const float2* wscA = sWsc + sp0 * 32 + w;
        const float2* wscB = sWsc + sp1 * 32 + w;
#pragma unroll 8
        for (int u = 0; u < 32; u++) {
            float4 xa = sBuf[warp][0][u];
            float4 xb = sBuf[warp][1][u];
            float2 ab = sW1[u * 32 + w];
            ysA = fmaf(xa.x, ab.x, ysA);  ysB = fmaf(xb.x, ab.x, ysB);
            y0A = fmaf(xa.y, ab.y, y0A);  y0B = fmaf(xb.y, ab.y, y0B);
            y1A = fmaf(xa.z, ab.y, y1A);  y1B = fmaf(xb.z, ab.y, y1B);
            y2A = fmaf(xa.w, ab.y, y2A);  y2B = fmaf(xb.w, ab.y, y2B);
            float2 ca = wscA[u * 128];
            float2 cb = wscB[u * 128];
            ssA = fmaf(xa.x, ca.x, ssA);  ssB = fmaf(xb.x, cb.x, ssB);
            s0A = fmaf(xa.y, ca.y, s0A);  s0B = fmaf(xb.y, cb.y, s0B);
            s1A = fmaf(xa.z, ca.y, s1A);  s1B = fmaf(xb.z, cb.y, s1B);
            s2A = fmaf(xa.w, ca.y, s2A);  s2B = fmaf(xb.w, cb.y, s2B);
        }

        g_y[n0 * 32 + w] = make_float4(ysA * l1n, y0A * l1n, y1A * l1n, y2A * l1n);
        g_y[n1 * 32 + w] = make_float4(ysB * l1n, y0B * l1n, y1B * l1n, y2B * l1n);

        float* o0 = out + (size_t)n0 * 128;
        o0[w] = ssA * scn;
        o0[32 + w * 3 + 0] = s0A * scn;
        o0[32 + w * 3 + 1] = s1A * scn;
        o0[32 + w * 3 + 2] = s2A * scn;
        float* o1 = out + (size_t)n1 * 128;
        o1[w] = ssB * scn;
        o1[32 + w * 3 + 0] = s0B * scn;
        o1[32 + w * 3 + 1] = s1B * scn;
        o1[32 + w * 3 + 2] = s2B * scn;
        __syncwarp();
    }
}

// ---------------------------------------------------------------------------
// Kernel 2: edge kernel. Warp per EDGE PAIR, lane = channel u.
// Scatter-add goes through TMA bulk reduction (cp.reduce.async.bulk):
// each edge's 1KB contribution staged in smem (double-buffered) and reduced
// into g_mid by the TMA engine — bypasses the per-lane LSU REDG bottleneck.
// Cooperative silu covers both edges in one MUFU pass (lanes 0-15).
// ---------------------------------------------------------------------------
__global__ void __launch_bounds__(256) edge_kernel(
                            const float* __restrict__ eb,
                            const float* __restrict__ ea,
                            const int* __restrict__ ei,
                            const float* __restrict__ fw1,
                            const float* __restrict__ fw2) {
    // [warp][parity][edge-in-pair][64 float4] = 32KB
    __shared__ float4 sbuf[8][2][2][64];

    const int tid = threadIdx.x;
    const int warp = tid >> 5, lane = tid & 31;
    const int nwarps = gridDim.x * 8;
    const float is8 = 0.3535533905932738f;  // 1/sqrt(8)
    const float IS3 = 0.5773502691896258f;  // 1/sqrt(3)
    const int u = lane;

    float w1r[8];
#pragma unroll
    for (int k = 0; k < 8; k++) w1r[k] = __ldg(fw1 + k * 8 + (lane & 7));
    float w2r[32];
#pragma unroll
    for (int j = 0; j < 8; j++)
#pragma unroll
        for (int c = 0; c < 4; c++)
            w2r[j * 4 + c] = __ldg(fw2 + j * 128 + c * 32 + u);

    int p = 0;
    const int ntasks = NE / 2;
    for (int t = blockIdx.x * 8 + warp; t < ntasks; t += nwarps) {
        const int e0 = 2 * t;
        const int2 src01 = __ldg((const int2*)(ei + e0));
        const int2 dst01 = __ldg((const int2*)(ei + NE + e0));

        const float4 ya  = __ldg(&g_y[src01.x * 32 + u]);
        const float4 yb  = __ldg(&g_y[src01.y * 32 + u]);
        const float4 av0 = __ldg((const float4*)(ea + (size_t)e0 * 4));
        const float4 av1 = __ldg((const float4*)(ea + (size_t)e0 * 4 + 4));

        // cooperative MLP layer 1 for BOTH edges: lanes 0-7 -> edge0,
        // lanes 8-15 -> edge1; one silu MUFU pass covers both.
        float ebv = (lane < 16)
            ? __ldg(eb + (size_t)(e0 + (lane >> 3)) * 8 + (lane & 7)) : 0.f;
        float acc = 0.f;
        const int gbase = lane & 8;   // 0 for edge0 lanes, 8 for edge1 lanes
#pragma unroll
        for (int k = 0; k < 8; k++)
            acc = fmaf(__shfl_sync(0xffffffffu, ebv, gbase + k), w1r[k], acc);
        acc *= is8;
        float hv = __fdividef(acc, 1.f + __expf(-acc));   // silu

        // layer 2 for both edges (register weights)
        float w00a = 0.f, w01a = 0.f, w10a = 0.f, w11a = 0.f;
        float w00b = 0.f, w01b = 0.f, w10b = 0.f, w11b = 0.f;
#pragma unroll
        for (int j = 0; j < 8; j++) {
            const float hj0 = __shfl_sync(0xffffffffu, hv, j);
            const float hj1 = __shfl_sync(0xffffffffu, hv, 8 + j);
            w00a = fmaf(hj0, w2r[j * 4 + 0], w00a);
            w01a = fmaf(hj0, w2r[j * 4 + 1], w01a);
            w10a = fmaf(hj0, w2r[j * 4 + 2], w10a);
            w11a = fmaf(hj0, w2r[j * 4 + 3], w11a);
            w00b = fmaf(hj1, w2r[j * 4 + 0], w00b);
            w01b = fmaf(hj1, w2r[j * 4 + 1], w01b);
            w10b = fmaf(hj1, w2r[j * 4 + 2], w10b);
            w11b = fmaf(hj1, w2r[j * 4 + 3], w11b);
        }

        // edge 0 outputs
        const float esa    = ya.x;
        const float dotva  = fmaf(ya.y, av0.y, fmaf(ya.z, av0.z, ya.w * av0.w));
        const float wesa   = w01a * is8 * esa;
        const float w10a0a = w10a * is8 * av0.x;
        float4 A0 = make_float4(w00a * is8 * esa * av0.x,
                                wesa * av0.y, wesa * av0.z, wesa * av0.w);
        float4 B0 = make_float4(w11a * is8 * dotva * IS3,
                                w10a0a * ya.y, w10a0a * ya.z, w10a0a * ya.w);
        // edge 1 outputs
        const float esb    = yb.x;
        const float dotvb  = fmaf(yb.y, av1.y, fmaf(yb.z, av1.z, yb.w * av1.w));
        const float wesb   = w01b * is8 * esb;
        const float w10a0b = w10b * is8 * av1.x;
        float4 A1 = make_float4(w00b * is8 * esb * av1.x,
                                wesb * av1.y, wesb * av1.z, wesb * av1.w);
        float4 B1 = make_float4(w11b * is8 * dotvb * IS3,
                                w10a0b * yb.y, w10a0b * yb.z, w10a0b * yb.w);

        // make sure buffer p's previous bulk-reduce has finished reading smem
        if (lane == 0)
            asm volatile("cp.async.bulk.wait_group.read 1;" ::: "memory");
        __syncwarp();

        sbuf[warp][p][0][lane * 2]     = A0;
        sbuf[warp][p][0][lane * 2 + 1] = B0;
        sbuf[warp][p][1][lane * 2]     = A1;
        sbuf[warp][p][1][lane * 2 + 1] = B1;
        __syncwarp();

        if (lane == 0) {
            asm volatile("fence.proxy.async.shared::cta;" ::: "memory");
            unsigned int s0 = (unsigned int)__cvta_generic_to_shared(&sbuf[warp][p][0][0]);
            unsigned int s1 = s0 + 1024u;
            asm volatile(
                "cp.reduce.async.bulk.global.shared::cta.bulk_group.add.f32 [%0], [%1], %2;"
                :: "l"(g_mid + (size_t)dst01.x * 64), "r"(s0), "r"(1024)
                : "memory");
            asm volatile(
                "cp.reduce.async.bulk.global.shared::cta.bulk_group.add.f32 [%0], [%1], %2;"
                :: "l"(g_mid + (size_t)dst01.y * 64), "r"(s1), "r"(1024)
                : "memory");
            asm volatile("cp.async.bulk.commit_group;" ::: "memory");
        }
        p ^= 1;
    }
    // TMA writes are flushed before kernel completion; nothing further needed.
}

// ---------------------------------------------------------------------------
// Kernel 3: per-node output, TWO nodes per warp. Reads interleaved g_mid;
// lin2 weights pre-permuted into smem so the inner loop stays identical.
//   interleaved row 2u   -> original W2 row u       (A channels)
//   interleaved row 2u+1 -> original W2 row 32+u    (B channels)
// ---------------------------------------------------------------------------
__global__ void node_out_kernel(const float* __restrict__ W2s,
                                const float* __restrict__ W2v,
                                float* __restrict__ out) {
    __shared__ float2 sW2[2048];      // permuted [uu][w]             16KB
    __shared__ float4 sMid[8][128];   // 2 nodes x 64 per warp        16KB

    const int tid = threadIdx.x;
    for (int i = tid; i < 2048; i += 256) {
        int uu = i >> 5, w = i & 31;
        int row = (uu & 1) ? (32 + (uu >> 1)) : (uu >> 1);
        sW2[i] = make_float2(W2s[row * 32 + w], W2v[row * 32 + w]);
    }
    __syncthreads();

    const int warp = tid >> 5, lane = tid & 31;
    const int nwarps = gridDim.x * 8;
    const float c = 0.25f * 0.125f;  // 1/sqrt(16) * 1/sqrt(64)

    for (int n0 = (blockIdx.x * 8 + warp) * 2; n0 < NN; n0 += nwarps * 2) {
        const int n1 = n0 + 1;

        sMid[warp][lane]       = g_mid[n0 * 64 + lane];
        sMid[warp][32 + lane]  = g_mid[n0 * 64 + 32 + lane];
        sMid[warp][64 + lane]  = g_mid[n1 * 64 + lane];
        sMid[warp][96 + lane]  = g_mid[n1 * 64 + 32 + lane];
        __syncwarp();

        const int w = lane;
        float osA = 0.f, v0A = 0.f, v1A = 0.f, v2A = 0.f;
        float osB = 0.f, v0B = 0.f, v1B = 0.f, v2B = 0.f;
#pragma unroll 16
        for (int uu = 0; uu < 64; uu++) {
            float4 ma = sMid[warp][uu];
            float4 mb = sMid[warp][64 + uu];
            float2 ab = sW2[uu * 32 + w];
            osA = fmaf(ma.x, ab.x, osA);  osB = fmaf(mb.x, ab.x, osB);
            v0A = fmaf(ma.y, ab.y, v0A);  v0B = fmaf(mb.y, ab.y, v0B);
            v1A = fmaf(ma.z, ab.y, v1A);  v1B = fmaf(mb.z, ab.y, v1B);
            v2A = fmaf(ma.w, ab.y, v2A);  v2B = fmaf(mb.w, ab.y, v2B);
        }

        float* o0 = out + (size_t)n0 * 128;
        o0[w]              += osA * c;
        o0[32 + w * 3 + 0] += v0A * c;
        o0[32 + w * 3 + 1] += v1A * c;
        o0[32 + w * 3 + 2] += v2A * c;
        float* o1 = out + (size_t)n1 * 128;
        o1[w]              += osB * c;
        o1[32 + w * 3 + 0] += v0B * c;
        o1[32 + w * 3 + 1] += v1B * c;
        o1[32 + w * 3 + 2] += v2B * c;
        __syncwarp();
    }
}

// ---------------------------------------------------------------------------
extern "C" void kernel_launch(void* const* d_in, const int* in_sizes, int n_in,
                              void* d_out, int out_size) {
    const float* nf    = (const float*)d_in[0];
    const float* nattr = (const float*)d_in[1];
    const float* eb    = (const float*)d_in[2];
    const float* ea    = (const float*)d_in[3];
    const int*   ei    = (const int*)d_in[4];
    const float* W1s   = (const float*)d_in[5];
    const float* W1v   = (const float*)d_in[6];
    const float* fw1   = (const float*)d_in[7];
    const float* fw2   = (const float*)d_in[8];
    const float* W2s   = (const float*)d_in[9];
    const float* W2v   = (const float*)d_in[10];
    const float* Wscs  = (const float*)d_in[11];
    const float* Wscv  = (const float*)d_in[12];
    float* out = (float*)d_out;

    node_prep_kernel<<<1184, 256>>>(nf, nattr, W1s, W1v, Wscs, Wscv, out);
    edge_kernel<<<1184, 256>>>(eb, ea, ei, fw1, fw2);
    node_out_kernel<<<1184, 256>>>(W2s, W2v, out);
}